// round 3
// baseline (speedup 1.0000x reference)
#include <cuda_runtime.h>
#include <math.h>

#define BATCH 8
#define NTOK  4096
#define CDIM  512
#define NHEAD 8
#define HH    4
#define HD    64

// ---------------- scratch (device globals; no allocation allowed) ----------
__device__ float g_xi [BATCH*CDIM*NTOK];        // x transposed to [B][C][H][W]
__device__ float g_q  [BATCH*NHEAD*NTOK*HD];    // q, head-major, pre-scaled
__device__ float g_x1 [BATCH*256*CDIM];         // branch1 tokens
__device__ float g_x2 [BATCH*1024*CDIM];        // branch2 tokens
__device__ float g_k1 [BATCH*HH*256*HD];
__device__ float g_v1 [BATCH*HH*256*HD];
__device__ float g_vm1[BATCH*HH*256*HD];
__device__ float g_k2 [BATCH*HH*1024*HD];
__device__ float g_v2 [BATCH*HH*1024*HD];
__device__ float g_vm2[BATCH*HH*1024*HD];
__device__ float g_ao [BATCH*NTOK*CDIM];        // concat attention output

// ---------------- transpose x: [B][N][C] -> [B][C][N] ----------------------
__global__ __launch_bounds__(1024) void k_transpose(const float* __restrict__ x)
{
    __shared__ float t[32][33];
    int b  = blockIdx.z;
    int c0 = blockIdx.x * 32;
    int n0 = blockIdx.y * 32;
    int tx = threadIdx.x, ty = threadIdx.y;
    t[ty][tx] = x[((size_t)b*NTOK + n0 + ty)*CDIM + c0 + tx];
    __syncthreads();
    g_xi[((size_t)b*CDIM + c0 + ty)*NTOK + n0 + tx] = t[tx][ty];
}

// ---------------- generic tiled SGEMM (64x64x16, 4x4 microtile) ------------
// MODE 0: proj:  A=g_ao,  C0[m*512+n] = acc + bias[n]
// MODE 1: q:     A=Aext,  g_q[((b*8+h)*4096+t)*64+d] = acc*alpha
// MODE 2: kv1:   A=g_x1,  (k1|v1)[((b*4+h)*256 +t)*64+d] = acc
// MODE 3: kv2:   A=g_x2,  (k2|v2)[((b*4+h)*1024+t)*64+d] = acc
template <int MODE>
__global__ __launch_bounds__(256) void k_sgemm(
    const float* __restrict__ Aext, const float* __restrict__ B,
    float* __restrict__ Cext, const float* __restrict__ bias, float alpha)
{
    const int K = CDIM, N = CDIM;
    const float* A = (MODE == 0) ? (const float*)g_ao :
                     (MODE == 1) ? Aext :
                     (MODE == 2) ? (const float*)g_x1 : (const float*)g_x2;

    __shared__ float As[16][65];
    __shared__ float Bs[16][64];
    int tid = threadIdx.x;
    int m0 = blockIdx.y * 64, n0 = blockIdx.x * 64;
    int tm = (tid >> 4) * 4, tn = (tid & 15) * 4;
    float acc[4][4];
#pragma unroll
    for (int i = 0; i < 4; i++)
#pragma unroll
        for (int j = 0; j < 4; j++) acc[i][j] = 0.f;

    for (int k0 = 0; k0 < K; k0 += 16) {
#pragma unroll
        for (int i = 0; i < 4; i++) {
            int idx = tid + i * 256;
            int ra = idx >> 4, ca = idx & 15;             // A: 64 rows x 16 k
            As[ca][ra] = A[(size_t)(m0 + ra) * K + k0 + ca];
            int rb = idx >> 6, cb = idx & 63;             // B: 16 k x 64 cols
            Bs[rb][cb] = B[(size_t)(k0 + rb) * N + n0 + cb];
        }
        __syncthreads();
#pragma unroll
        for (int kk = 0; kk < 16; kk++) {
            float av[4], bv[4];
#pragma unroll
            for (int i = 0; i < 4; i++) av[i] = As[kk][tm + i];
#pragma unroll
            for (int j = 0; j < 4; j++) bv[j] = Bs[kk][tn + j];
#pragma unroll
            for (int i = 0; i < 4; i++)
#pragma unroll
                for (int j = 0; j < 4; j++) acc[i][j] += av[i] * bv[j];
        }
        __syncthreads();
    }

#pragma unroll
    for (int i = 0; i < 4; i++)
#pragma unroll
        for (int j = 0; j < 4; j++) {
            int m = m0 + tm + i, n = n0 + tn + j;
            float v = acc[i][j];
            if (MODE == 0) {
                Cext[(size_t)m * N + n] = v + bias[n];
            } else if (MODE == 1) {
                int b = m >> 12, t = m & 4095;
                int h = n >> 6, d = n & 63;
                g_q[(((size_t)(b * NHEAD + h)) * NTOK + t) * HD + d] = v * alpha;
            } else if (MODE == 2) {
                int b = m >> 8, t = m & 255;
                int a = n >> 8, h = (n >> 6) & 3, d = n & 63;
                float* dst = a ? g_v1 : g_k1;
                dst[(((size_t)(b * HH + h)) * 256 + t) * HD + d] = v;
            } else {
                int b = m >> 10, t = m & 1023;
                int a = n >> 8, h = (n >> 6) & 3, d = n & 63;
                float* dst = a ? g_v2 : g_k2;
                dst[(((size_t)(b * HH + h)) * 1024 + t) * HD + d] = v;
            }
        }
}

// ---------------- strided conv (direct, smem tiled) ------------------------
// out token-major [b][tok][co]; co tile = 32, spatial tile = OHT*OW = 256.
template <int KS, int STRIDE, int OW, int OHT, int BR>
__global__ __launch_bounds__(256) void k_conv(
    const float* __restrict__ w, const float* __restrict__ bias)
{
    const int IHT = (OHT - 1) * STRIDE + KS;
    const int NT  = BR ? 1024 : 256;
    float* out = BR ? g_x2 : g_x1;
    __shared__ float tin[IHT][66];
    __shared__ float tw[32][KS * KS];
    int b = blockIdx.z, co0 = blockIdx.x * 32, oh0 = blockIdx.y * OHT;
    int tid = threadIdx.x;
    int cog = tid & 7, spg = tid >> 3;
    int iy0 = oh0 * STRIDE - 1;

    float acc[4][8];
#pragma unroll
    for (int j = 0; j < 4; j++)
#pragma unroll
        for (int s = 0; s < 8; s++) acc[j][s] = 0.f;

    for (int ci = 0; ci < CDIM; ci++) {
        const float* src = g_xi + ((size_t)b * CDIM + ci) * NTOK;
        for (int idx = tid; idx < IHT * 65; idx += 256) {
            int r = idx / 65, c = idx % 65;
            int iy = iy0 + r, ix = c - 1;
            float v = 0.f;
            if (iy >= 0 && iy < 64 && ix >= 0) v = src[iy * 64 + ix];
            tin[r][c] = v;
        }
        for (int idx = tid; idx < 32 * KS * KS; idx += 256) {
            int r = idx / (KS * KS), t = idx % (KS * KS);
            tw[r][t] = w[((size_t)(co0 + r) * CDIM + ci) * (KS * KS) + t];
        }
        __syncthreads();
#pragma unroll
        for (int ky = 0; ky < KS; ky++)
#pragma unroll
            for (int kx = 0; kx < KS; kx++) {
                float w4[4];
#pragma unroll
                for (int j = 0; j < 4; j++) w4[j] = tw[cog * 4 + j][ky * KS + kx];
#pragma unroll
                for (int s = 0; s < 8; s++) {
                    int sp = spg * 8 + s;
                    int oy = sp / OW, ox = sp % OW;
                    float in = tin[oy * STRIDE + ky][ox * STRIDE + kx];
#pragma unroll
                    for (int j = 0; j < 4; j++) acc[j][s] += w4[j] * in;
                }
            }
        __syncthreads();
    }

#pragma unroll
    for (int s = 0; s < 8; s++) {
        int sp = spg * 8 + s;
        int oy = sp / OW, ox = sp % OW;
        int tok = (oh0 + oy) * OW + ox;
#pragma unroll
        for (int j = 0; j < 4; j++) {
            int co = co0 + cog * 4 + j;
            out[((size_t)b * NT + tok) * CDIM + co] = acc[j][s] + bias[co];
        }
    }
}

// ---------------- LayerNorm + exact GELU, in place -------------------------
__device__ __forceinline__ float gelu_exact(float y)
{
    return 0.5f * y * (1.f + erff(y * 0.70710678118654752f));
}

template <int BR>
__global__ __launch_bounds__(256) void k_ln_gelu(
    const float* __restrict__ w, const float* __restrict__ b)
{
    float* base = BR ? g_x2 : g_x1;
    size_t t = blockIdx.x;
    float* row = base + t * CDIM;
    int tid = threadIdx.x;
    float v0 = row[tid], v1 = row[tid + 256];
    float s = v0 + v1, ss = v0 * v0 + v1 * v1;
#pragma unroll
    for (int o = 16; o; o >>= 1) {
        s  += __shfl_xor_sync(0xffffffffu, s, o);
        ss += __shfl_xor_sync(0xffffffffu, ss, o);
    }
    __shared__ float rs[8], rss[8];
    if ((tid & 31) == 0) { rs[tid >> 5] = s; rss[tid >> 5] = ss; }
    __syncthreads();
    if (tid < 32) {
        float a = (tid < 8) ? rs[tid] : 0.f;
        float c = (tid < 8) ? rss[tid] : 0.f;
#pragma unroll
        for (int o = 4; o; o >>= 1) {
            a += __shfl_xor_sync(0xffffffffu, a, o);
            c += __shfl_xor_sync(0xffffffffu, c, o);
        }
        if (tid == 0) { rs[0] = a; rss[0] = c; }
    }
    __syncthreads();
    float mean = rs[0] * (1.f / CDIM);
    float var  = rss[0] * (1.f / CDIM) - mean * mean;
    float inv  = rsqrtf(var + 1e-5f);
    float y0 = (v0 - mean) * inv * w[tid] + b[tid];
    float y1 = (v1 - mean) * inv * w[tid + 256] + b[tid + 256];
    row[tid]       = gelu_exact(y0);
    row[tid + 256] = gelu_exact(y1);
}

// ---------------- depthwise 3x3 local conv on v, fused v+lv ----------------
// v/vm: [B][HH][h*w][HD]; weight channel: ch = a*128 + c*4 + head (d=a*32+c)
template <int BR>
__global__ __launch_bounds__(256) void k_lvadd(
    const float* __restrict__ lcw, const float* __restrict__ lcb)
{
    const int WW = BR ? 32 : 16;
    const int HWN = WW * WW;
    const float* v = BR ? g_v2 : g_v1;
    float* vm      = BR ? g_vm2 : g_vm1;
    int idx = blockIdx.x * 256 + threadIdx.x;
    int d = idx & 63;
    int tok = (idx >> 6) % HWN;
    int head = (idx / (64 * HWN)) & 3;
    int y = tok / WW, x = tok % WW;
    int a = d >> 5, c = d & 31;
    int ch = a * 128 + c * 4 + head;
    const float* base = v + ((size_t)idx - (size_t)tok * 64 - d);
    float accv = lcb[ch];
#pragma unroll
    for (int ky = 0; ky < 3; ky++) {
        int yy = y + ky - 1;
        if (yy < 0 || yy >= WW) continue;
#pragma unroll
        for (int kx = 0; kx < 3; kx++) {
            int xx = x + kx - 1;
            if (xx < 0 || xx >= WW) continue;
            accv += lcw[ch * 9 + ky * 3 + kx] * base[((size_t)yy * WW + xx) * 64 + d];
        }
    }
    vm[idx] = v[idx] + accv;
}

// ---------------- attention: 32-query tile, scores in smem -----------------
// smem: sQ[32*64] | sKV[64*65] | sS[32*NKV]
template <int BR>
__global__ __launch_bounds__(256) void k_attn()
{
    const int NKV = BR ? 1024 : 256;
    const int HOFF = BR ? 4 : 0;
    const int COLB = BR ? 256 : 0;
    const float* k = BR ? g_k2 : g_k1;
    const float* v = BR ? g_vm2 : g_vm1;

    extern __shared__ float sm[];
    float* sQ  = sm;
    float* sKV = sm + 32 * 64;
    float* sS  = sm + 32 * 64 + 64 * 65;

    int b = blockIdx.z, h = blockIdx.y;
    int qb = blockIdx.x * 32;
    int tid = threadIdx.x;
    int tq = tid >> 4, tn = tid & 15;
    int q0 = tq * 2, c0 = tn * 4;

    const float* qbase = g_q + (((size_t)(b * NHEAD + HOFF + h)) * NTOK + qb) * HD;
    const float* kbase = k + ((size_t)(b * HH + h)) * NKV * HD;
    const float* vbase = v + ((size_t)(b * HH + h)) * NKV * HD;

    for (int i = tid; i < 32 * 64; i += 256) sQ[i] = qbase[i];

    const int nc = NKV >> 6;
#pragma unroll 1
    for (int kc = 0; kc < nc; kc++) {
        for (int i = tid; i < 64 * 64; i += 256) {
            int r = i >> 6, d = i & 63;
            sKV[r * 65 + d] = kbase[((size_t)(kc * 64 + r)) * 64 + d];
        }
        __syncthreads();
        float s2[2][4];
#pragma unroll
        for (int i = 0; i < 2; i++)
#pragma unroll
            for (int j = 0; j < 4; j++) s2[i][j] = 0.f;
#pragma unroll 8
        for (int d = 0; d < 64; d++) {
            float qv0 = sQ[q0 * 64 + d], qv1 = sQ[(q0 + 1) * 64 + d];
            float kv[4];
#pragma unroll
            for (int j = 0; j < 4; j++) kv[j] = sKV[(c0 + j) * 65 + d];
#pragma unroll
            for (int j = 0; j < 4; j++) { s2[0][j] += qv0 * kv[j]; s2[1][j] += qv1 * kv[j]; }
        }
#pragma unroll
        for (int i = 0; i < 2; i++)
#pragma unroll
            for (int j = 0; j < 4; j++)
                sS[(q0 + i) * NKV + kc * 64 + c0 + j] = s2[i][j];
        __syncthreads();
    }

    // softmax: 8 lanes per row
    {
        int row = tid >> 3, l8 = tid & 7;
        float* srow = sS + row * NKV;
        float mx = -1e30f;
        for (int j = l8; j < NKV; j += 8) mx = fmaxf(mx, srow[j]);
#pragma unroll
        for (int o = 1; o < 8; o <<= 1) mx = fmaxf(mx, __shfl_xor_sync(0xffffffffu, mx, o));
        float sum = 0.f;
        for (int j = l8; j < NKV; j += 8) { float e = __expf(srow[j] - mx); srow[j] = e; sum += e; }
#pragma unroll
        for (int o = 1; o < 8; o <<= 1) sum += __shfl_xor_sync(0xffffffffu, sum, o);
        float inv = 1.f / sum;
        for (int j = l8; j < NKV; j += 8) srow[j] *= inv;
    }
    __syncthreads();

    // O = P @ V
    float o2[2][4];
#pragma unroll
    for (int i = 0; i < 2; i++)
#pragma unroll
        for (int j = 0; j < 4; j++) o2[i][j] = 0.f;
#pragma unroll 1
    for (int kc = 0; kc < nc; kc++) {
        for (int i = tid; i < 64 * 64; i += 256) {
            int r = i >> 6, d = i & 63;
            sKV[r * 65 + d] = vbase[((size_t)(kc * 64 + r)) * 64 + d];
        }
        __syncthreads();
#pragma unroll 8
        for (int kk = 0; kk < 64; kk++) {
            float p0 = sS[q0 * NKV + kc * 64 + kk];
            float p1 = sS[(q0 + 1) * NKV + kc * 64 + kk];
            float vv[4];
#pragma unroll
            for (int j = 0; j < 4; j++) vv[j] = sKV[kk * 65 + c0 + j];
#pragma unroll
            for (int j = 0; j < 4; j++) { o2[0][j] += p0 * vv[j]; o2[1][j] += p1 * vv[j]; }
        }
        __syncthreads();
    }
#pragma unroll
    for (int i = 0; i < 2; i++)
#pragma unroll
        for (int j = 0; j < 4; j++)
            g_ao[((size_t)b * NTOK + qb + q0 + i) * CDIM + COLB + h * 64 + c0 + j] = o2[i][j];
}

// ---------------- launch ----------------------------------------------------
extern "C" void kernel_launch(void* const* d_in, const int* in_sizes, int n_in,
                              void* d_out, int out_size)
{
    (void)in_sizes; (void)n_in; (void)out_size;
    const float* x       = (const float*)d_in[0];
    const float* q_w     = (const float*)d_in[3];
    const float* sr1_w   = (const float*)d_in[4];
    const float* sr1_b   = (const float*)d_in[5];
    const float* norm1_w = (const float*)d_in[6];
    const float* norm1_b = (const float*)d_in[7];
    const float* sr2_w   = (const float*)d_in[8];
    const float* sr2_b   = (const float*)d_in[9];
    const float* norm2_w = (const float*)d_in[10];
    const float* norm2_b = (const float*)d_in[11];
    const float* kv1_w   = (const float*)d_in[12];
    const float* kv2_w   = (const float*)d_in[13];
    const float* lc1_w   = (const float*)d_in[14];
    const float* lc1_b   = (const float*)d_in[15];
    const float* lc2_w   = (const float*)d_in[16];
    const float* lc2_b   = (const float*)d_in[17];
    const float* proj_w  = (const float*)d_in[18];
    const float* proj_b  = (const float*)d_in[19];

    static bool attr_done = false;
    if (!attr_done) {
        cudaFuncSetAttribute(k_attn<0>, cudaFuncAttributeMaxDynamicSharedMemorySize, 60000);
        cudaFuncSetAttribute(k_attn<1>, cudaFuncAttributeMaxDynamicSharedMemorySize, 160000);
        attr_done = true;
    }

    // x -> NCHW
    k_transpose<<<dim3(16, 128, 8), dim3(32, 32)>>>(x);

    // q = (x @ q_w) * scale, head-major scatter
    k_sgemm<1><<<dim3(8, 512), 256>>>(x, q_w, nullptr, nullptr, 0.125f);

    // SR convs
    k_conv<5, 4, 16, 16, 0><<<dim3(16, 1, 8), 256>>>(sr1_w, sr1_b);
    k_conv<3, 2, 32, 8, 1> <<<dim3(16, 4, 8), 256>>>(sr2_w, sr2_b);

    // LN + GELU (in place)
    k_ln_gelu<0><<<8 * 256, 256>>>(norm1_w, norm1_b);
    k_ln_gelu<1><<<8 * 1024, 256>>>(norm2_w, norm2_b);

    // kv projections, scattered into head-major k/v
    k_sgemm<2><<<dim3(8, 32), 256>>>(nullptr, kv1_w, nullptr, nullptr, 1.f);
    k_sgemm<3><<<dim3(8, 128), 256>>>(nullptr, kv2_w, nullptr, nullptr, 1.f);

    // v = v + depthwise_conv(v)
    k_lvadd<0><<<(8 * 4 * 256 * 64) / 256, 256>>>(lc1_w, lc1_b);
    k_lvadd<1><<<(8 * 4 * 1024 * 64) / 256, 256>>>(lc2_w, lc2_b);

    // attention (scores in smem; branch1 n=256, branch2 n=1024)
    size_t smem1 = (size_t)(32 * 64 + 64 * 65 + 32 * 256) * 4;
    size_t smem2 = (size_t)(32 * 64 + 64 * 65 + 32 * 1024) * 4;
    k_attn<0><<<dim3(128, 4, 8), 256, smem1>>>();
    k_attn<1><<<dim3(128, 4, 8), 256, smem2>>>();

    // out projection + bias
    k_sgemm<0><<<dim3(8, 512), 256>>>(nullptr, proj_w, (float*)d_out, proj_b, 1.f);
}

// round 5
// speedup vs baseline: 2.0346x; 2.0346x over previous
#include <cuda_runtime.h>
#include <math.h>

#define BATCH 8
#define NTOK  4096
#define CDIM  512
#define NHEAD 8
#define HH    4
#define HD    64

// ---------------- scratch (device globals; no allocation allowed) ----------
__device__ float g_xi [BATCH*CDIM*NTOK];        // x as [B][C][H][W]
__device__ float g_q  [BATCH*NHEAD*NTOK*HD];    // q, head-major, pre-scaled
__device__ float g_x1 [BATCH*256*CDIM];
__device__ float g_x2 [BATCH*1024*CDIM];
__device__ float g_k1 [BATCH*HH*256*HD];
__device__ float g_v1 [BATCH*HH*256*HD];
__device__ float g_vm1[BATCH*HH*256*HD];
__device__ float g_k2 [BATCH*HH*1024*HD];
__device__ float g_v2 [BATCH*HH*1024*HD];
__device__ float g_vm2[BATCH*HH*1024*HD];
__device__ float g_ao [BATCH*NTOK*CDIM];
__device__ float g_cp [4*2048*CDIM];            // conv1 split-K partials

// ---------------- fast exp (FMA pipe, avoids MUFU throughput wall) ---------
__device__ __forceinline__ float fast_exp(float x)
{
    x = fmaxf(x, -80.f);
    float t = fmaf(x, 1.4426950408889634f, 12582912.f);
    float n = t - 12582912.f;                       // round(x*log2e)
    float r = fmaf(n, -0.693359375f, x);            // x - n*ln2_hi
    r = fmaf(n, 2.1219444005469058e-4f, r);
    float p = fmaf(r, 8.3333337e-3f, 4.1666668e-2f);
    p = fmaf(p, r, 0.16666667f);
    p = fmaf(p, r, 0.5f);
    p = fmaf(p, r, 1.0f);
    p = fmaf(p, r, 1.0f);
    int e = (int)n;
    float s = __int_as_float((e + 127) << 23);
    return p * s;
}

// ---------------- transpose x: [B][N][C] -> [B][C][N] ----------------------
__global__ __launch_bounds__(1024) void k_transpose(const float* __restrict__ x)
{
    __shared__ float t[32][33];
    int b  = blockIdx.z;
    int c0 = blockIdx.x * 32;
    int n0 = blockIdx.y * 32;
    int tx = threadIdx.x, ty = threadIdx.y;
    t[ty][tx] = x[((size_t)b*NTOK + n0 + ty)*CDIM + c0 + tx];
    __syncthreads();
    g_xi[((size_t)b*CDIM + c0 + ty)*NTOK + n0 + tx] = t[tx][ty];
}

// ---------------- unified tiled GEMM (128x128 tile, 8x8 microtile) ---------
// AM: A source   0 ext[M][512] | 10 g_x1 | 11 g_x2 | 12 g_ao | 1 conv gather
// BM: B source   0 ext [K][N] ld=512 | 1 ext weights [N][K] ld=512*KS2
// EM: epilogue   0 ext C+bias | 1 q-scatter*0.125 | 2 kv1-scatter | 3 kv2-scatter
//                4 splitK partial->g_cp | 6 ->g_x2 +bias
template<int AM,int BM,int EM,int KS,int STR,int NT>
__global__ __launch_bounds__(256) void k_gemm(
    const float* __restrict__ Ae, const float* __restrict__ Be,
    float* __restrict__ Ce, const float* __restrict__ bias,
    int nchunk, int kzst)
{
    constexpr int KS2 = (KS > 0) ? KS * KS : 1;
    __shared__ float As[16][132];
    __shared__ float Bs[16][132];
    const int tid = threadIdx.x;
    const int m0 = blockIdx.y * 128, n0 = blockIdx.x * 128;
    const int z = blockIdx.z;
    const int tx = tid & 15, ty = tid >> 4;

    float acc[8][8];
#pragma unroll
    for (int i = 0; i < 8; i++)
#pragma unroll
        for (int j = 0; j < 8; j++) acc[i][j] = 0.f;

    for (int kc = 0; kc < nchunk; kc++) {
        int k0 = z * kzst + kc * 16;
        __syncthreads();
#pragma unroll
        for (int e = 0; e < 8; e++) {
            int idx = tid + e * 256;
            int kk = idx & 15, r = idx >> 4;
            int k = k0 + kk, m = m0 + r;
            float v;
            if (AM == 0)       v = Ae[(size_t)m * CDIM + k];
            else if (AM == 10) v = g_x1[(size_t)m * CDIM + k];
            else if (AM == 11) v = g_x2[(size_t)m * CDIM + k];
            else if (AM == 12) v = g_ao[(size_t)m * CDIM + k];
            else { // conv gather
                int b, tok, oy, ox;
                if (NT == 256) { b = m >> 8;  tok = m & 255;  oy = tok >> 4; ox = tok & 15; }
                else           { b = m >> 10; tok = m & 1023; oy = tok >> 5; ox = tok & 31; }
                int ci = k / KS2, tt = k - ci * KS2;
                int ky = tt / KS, kx = tt - ky * KS;
                int iy = oy * STR + ky - 1, ix = ox * STR + kx - 1;
                v = (iy >= 0 && iy < 64 && ix >= 0 && ix < 64)
                    ? g_xi[(((size_t)b * CDIM + ci) * 64 + iy) * 64 + ix] : 0.f;
            }
            As[kk][r] = v;
        }
#pragma unroll
        for (int e = 0; e < 8; e++) {
            int idx = tid + e * 256;
            int kk, c;
            if (BM == 0) { c = idx & 127; kk = idx >> 7; }
            else         { kk = idx & 15; c = idx >> 4; }
            int k = k0 + kk, n = n0 + c;
            float v;
            if (BM == 0) v = Be[(size_t)k * CDIM + n];
            else         v = Be[(size_t)n * (CDIM * KS2) + k];
            Bs[kk][c] = v;
        }
        __syncthreads();
#pragma unroll
        for (int kk = 0; kk < 16; kk++) {
            float a[8], b[8];
#pragma unroll
            for (int i = 0; i < 8; i++) a[i] = As[kk][ty * 8 + i];
#pragma unroll
            for (int j = 0; j < 8; j++) b[j] = Bs[kk][tx * 8 + j];
#pragma unroll
            for (int i = 0; i < 8; i++)
#pragma unroll
                for (int j = 0; j < 8; j++) acc[i][j] = fmaf(a[i], b[j], acc[i][j]);
        }
    }

#pragma unroll
    for (int i = 0; i < 8; i++) {
        int m = m0 + ty * 8 + i;
#pragma unroll
        for (int j = 0; j < 8; j++) {
            int n = n0 + tx * 8 + j;
            float v = acc[i][j];
            if (EM == 0) Ce[(size_t)m * CDIM + n] = v + bias[n];
            else if (EM == 1) {
                int b = m >> 12, t = m & 4095, h = n >> 6, d = n & 63;
                g_q[(((size_t)(b * NHEAD + h)) * NTOK + t) * HD + d] = v * 0.125f;
            } else if (EM == 2) {
                int b = m >> 8, t = m & 255, a2 = n >> 8, h = (n >> 6) & 3, d = n & 63;
                (a2 ? g_v1 : g_k1)[(((size_t)(b * HH + h)) * 256 + t) * HD + d] = v;
            } else if (EM == 3) {
                int b = m >> 10, t = m & 1023, a2 = n >> 8, h = (n >> 6) & 3, d = n & 63;
                (a2 ? g_v2 : g_k2)[(((size_t)(b * HH + h)) * 1024 + t) * HD + d] = v;
            } else if (EM == 4) {
                g_cp[((size_t)z * 2048 + m) * CDIM + n] = v;
            } else { // EM == 6
                g_x2[(size_t)m * CDIM + n] = v + bias[n];
            }
        }
    }
}

// ---------------- conv1 split-K reduce + bias ------------------------------
__global__ __launch_bounds__(256) void k_red4(const float* __restrict__ bias)
{
    int i = blockIdx.x * 256 + threadIdx.x;   // over 2048*512
    float v = g_cp[i] + g_cp[i + 2048*CDIM] + g_cp[i + 2*2048*CDIM] + g_cp[i + 3*2048*CDIM];
    g_x1[i] = v + bias[i & 511];
}

// ---------------- flash attention: 64-query tile, online softmax -----------
// grid: (NTOK/64, B*HH); block 256 = 16x16 of 4x4 microtiles
template<int NKV, int BR>
__global__ __launch_bounds__(256) void k_flash()
{
    extern __shared__ float sm[];
    float* sQ = sm;                 // [64][68] transposed: sQ[d*68+q]
    float* sK = sm + 64*68;         // sK[d*68+kv]
    float* sV = sm + 2*64*68;       // sV[kv*68+d]
    float* sP = sm + 3*64*68;       // sP[kv*68+q]

    const int z = blockIdx.y;       // b*4 + h_local
    const int q0 = blockIdx.x * 64;
    const int b = z >> 2, hl = z & 3;
    const float* qb = g_q + (((size_t)(b * NHEAD + hl + (BR ? 4 : 0))) * NTOK + q0) * HD;
    const float* kb = (BR ? g_k2  : g_k1 ) + (size_t)z * NKV * HD;
    const float* vb = (BR ? g_vm2 : g_vm1) + (size_t)z * NKV * HD;

    const int tid = threadIdx.x;
    const int tx = tid & 15, ty = tid >> 4;

    for (int i = tid; i < 64 * 64; i += 256) {
        int q = i >> 6, d = i & 63;
        sQ[d * 68 + q] = qb[i];
    }

    float m4[4], l4[4], o4[4][4];
#pragma unroll
    for (int i = 0; i < 4; i++) {
        m4[i] = -1e30f; l4[i] = 0.f;
#pragma unroll
        for (int j = 0; j < 4; j++) o4[i][j] = 0.f;
    }

    const int nc = NKV / 64;
    for (int kc = 0; kc < nc; kc++) {
        __syncthreads();
        for (int i = tid; i < 64 * 64; i += 256) {
            int r = i >> 6, d = i & 63;
            float kvv = kb[(size_t)(kc * 64) * 64 + i];
            sK[d * 68 + r] = kvv;
            sV[r * 68 + d] = vb[(size_t)(kc * 64) * 64 + i];
        }
        __syncthreads();

        // S = Q K^T (q pre-scaled)
        float s[4][4];
#pragma unroll
        for (int i = 0; i < 4; i++)
#pragma unroll
            for (int j = 0; j < 4; j++) s[i][j] = 0.f;
#pragma unroll 4
        for (int d = 0; d < 64; d++) {
            float a[4], bq[4];
#pragma unroll
            for (int i = 0; i < 4; i++) a[i]  = sQ[d * 68 + ty * 4 + i];
#pragma unroll
            for (int j = 0; j < 4; j++) bq[j] = sK[d * 68 + tx * 4 + j];
#pragma unroll
            for (int i = 0; i < 4; i++)
#pragma unroll
                for (int j = 0; j < 4; j++) s[i][j] = fmaf(a[i], bq[j], s[i][j]);
        }

        // online softmax update (reduce over 16-lane row groups)
#pragma unroll
        for (int i = 0; i < 4; i++) {
            float mx = fmaxf(fmaxf(s[i][0], s[i][1]), fmaxf(s[i][2], s[i][3]));
#pragma unroll
            for (int o = 1; o < 16; o <<= 1)
                mx = fmaxf(mx, __shfl_xor_sync(0xffffffffu, mx, o));
            float mnew = fmaxf(m4[i], mx);
            float corr = fast_exp(m4[i] - mnew);
            float ls = 0.f;
#pragma unroll
            for (int j = 0; j < 4; j++) {
                float p = fast_exp(s[i][j] - mnew);
                s[i][j] = p;
                ls += p;
            }
#pragma unroll
            for (int o = 1; o < 16; o <<= 1)
                ls += __shfl_xor_sync(0xffffffffu, ls, o);
            l4[i] = l4[i] * corr + ls;
            m4[i] = mnew;
#pragma unroll
            for (int j = 0; j < 4; j++) o4[i][j] *= corr;
        }

        // write P transposed: sP[kv][q]
#pragma unroll
        for (int i = 0; i < 4; i++)
#pragma unroll
            for (int j = 0; j < 4; j++)
                sP[(tx * 4 + j) * 68 + ty * 4 + i] = s[i][j];
        __syncthreads();

        // O += P V
#pragma unroll 4
        for (int kk = 0; kk < 64; kk++) {
            float a[4], bv[4];
#pragma unroll
            for (int i = 0; i < 4; i++) a[i]  = sP[kk * 68 + ty * 4 + i];
#pragma unroll
            for (int j = 0; j < 4; j++) bv[j] = sV[kk * 68 + tx * 4 + j];
#pragma unroll
            for (int i = 0; i < 4; i++)
#pragma unroll
                for (int j = 0; j < 4; j++) o4[i][j] = fmaf(a[i], bv[j], o4[i][j]);
        }
    }

    const int colb = (BR ? 256 : 0) + hl * 64;
#pragma unroll
    for (int i = 0; i < 4; i++) {
        float inv = 1.f / l4[i];
        int q = q0 + ty * 4 + i;
#pragma unroll
        for (int j = 0; j < 4; j++)
            g_ao[((size_t)b * NTOK + q) * CDIM + colb + tx * 4 + j] = o4[i][j] * inv;
    }
}

// ---------------- LayerNorm + exact GELU, in place -------------------------
__device__ __forceinline__ float gelu_exact(float y)
{
    return 0.5f * y * (1.f + erff(y * 0.70710678118654752f));
}

template <int BR>
__global__ __launch_bounds__(256) void k_ln_gelu(
    const float* __restrict__ w, const float* __restrict__ b)
{
    float* base = BR ? g_x2 : g_x1;
    size_t t = blockIdx.x;
    float* row = base + t * CDIM;
    int tid = threadIdx.x;
    float v0 = row[tid], v1 = row[tid + 256];
    float s = v0 + v1, ss = v0 * v0 + v1 * v1;
#pragma unroll
    for (int o = 16; o; o >>= 1) {
        s  += __shfl_xor_sync(0xffffffffu, s, o);
        ss += __shfl_xor_sync(0xffffffffu, ss, o);
    }
    __shared__ float rs[8], rss[8];
    if ((tid & 31) == 0) { rs[tid >> 5] = s; rss[tid >> 5] = ss; }
    __syncthreads();
    if (tid < 32) {
        float a = (tid < 8) ? rs[tid] : 0.f;
        float c = (tid < 8) ? rss[tid] : 0.f;
#pragma unroll
        for (int o = 4; o; o >>= 1) {
            a += __shfl_xor_sync(0xffffffffu, a, o);
            c += __shfl_xor_sync(0xffffffffu, c, o);
        }
        if (tid == 0) { rs[0] = a; rss[0] = c; }
    }
    __syncthreads();
    float mean = rs[0] * (1.f / CDIM);
    float var  = rss[0] * (1.f / CDIM) - mean * mean;
    float inv  = rsqrtf(var + 1e-5f);
    float y0 = (v0 - mean) * inv * w[tid] + b[tid];
    float y1 = (v1 - mean) * inv * w[tid + 256] + b[tid + 256];
    row[tid]       = gelu_exact(y0);
    row[tid + 256] = gelu_exact(y1);
}

// ---------------- depthwise 3x3 local conv on v, fused v+lv ----------------
template <int BR>
__global__ __launch_bounds__(256) void k_lvadd(
    const float* __restrict__ lcw, const float* __restrict__ lcb)
{
    const int WW = BR ? 32 : 16;
    const int HWN = WW * WW;
    const float* v = BR ? g_v2 : g_v1;
    float* vm      = BR ? g_vm2 : g_vm1;
    int idx = blockIdx.x * 256 + threadIdx.x;
    int d = idx & 63;
    int tok = (idx >> 6) % HWN;
    int head = (idx / (64 * HWN)) & 3;
    int y = tok / WW, x = tok % WW;
    int a = d >> 5, c = d & 31;
    int ch = a * 128 + c * 4 + head;
    const float* base = v + ((size_t)idx - (size_t)tok * 64 - d);
    float accv = lcb[ch];
#pragma unroll
    for (int ky = 0; ky < 3; ky++) {
        int yy = y + ky - 1;
        if (yy < 0 || yy >= WW) continue;
#pragma unroll
        for (int kx = 0; kx < 3; kx++) {
            int xx = x + kx - 1;
            if (xx < 0 || xx >= WW) continue;
            accv += lcw[ch * 9 + ky * 3 + kx] * base[((size_t)yy * WW + xx) * 64 + d];
        }
    }
    vm[idx] = v[idx] + accv;
}

// ---------------- launch ----------------------------------------------------
extern "C" void kernel_launch(void* const* d_in, const int* in_sizes, int n_in,
                              void* d_out, int out_size)
{
    (void)in_sizes; (void)n_in; (void)out_size;
    const float* x       = (const float*)d_in[0];
    const float* q_w     = (const float*)d_in[3];
    const float* sr1_w   = (const float*)d_in[4];
    const float* sr1_b   = (const float*)d_in[5];
    const float* norm1_w = (const float*)d_in[6];
    const float* norm1_b = (const float*)d_in[7];
    const float* sr2_w   = (const float*)d_in[8];
    const float* sr2_b   = (const float*)d_in[9];
    const float* norm2_w = (const float*)d_in[10];
    const float* norm2_b = (const float*)d_in[11];
    const float* kv1_w   = (const float*)d_in[12];
    const float* kv2_w   = (const float*)d_in[13];
    const float* lc1_w   = (const float*)d_in[14];
    const float* lc1_b   = (const float*)d_in[15];
    const float* lc2_w   = (const float*)d_in[16];
    const float* lc2_b   = (const float*)d_in[17];
    const float* proj_w  = (const float*)d_in[18];
    const float* proj_b  = (const float*)d_in[19];

    static bool attr_done = false;
    if (!attr_done) {
        cudaFuncSetAttribute(k_flash<256, 0>,
                             cudaFuncAttributeMaxDynamicSharedMemorySize, 70000);
        cudaFuncSetAttribute(k_flash<1024, 1>,
                             cudaFuncAttributeMaxDynamicSharedMemorySize, 70000);
        attr_done = true;
    }
    const size_t fl_smem = (size_t)4 * 64 * 68 * 4;

    // x -> NCHW
    k_transpose<<<dim3(16, 128, 8), dim3(32, 32)>>>(x);

    // q = (x @ q_w) * 0.125, head-major scatter
    k_gemm<0,0,1, 0,0,0><<<dim3(4,256,1), 256>>>(x, q_w, nullptr, nullptr, 32, 0);

    // conv1 as implicit GEMM, split-K x4, then reduce (+bias)
    k_gemm<1,1,4, 5,4,256><<<dim3(4,16,4), 256>>>(nullptr, sr1_w, nullptr, nullptr, 200, 3200);
    k_red4<<<2048*CDIM/256, 256>>>(sr1_b);

    // conv2 as implicit GEMM (+bias)
    k_gemm<1,1,6, 3,2,1024><<<dim3(4,64,1), 256>>>(nullptr, sr2_w, nullptr, sr2_b, 288, 0);

    // LN + GELU (in place)
    k_ln_gelu<0><<<8 * 256, 256>>>(norm1_w, norm1_b);
    k_ln_gelu<1><<<8 * 1024, 256>>>(norm2_w, norm2_b);

    // kv projections, head-major scatter
    k_gemm<10,0,2, 0,0,0><<<dim3(4,16,1), 256>>>(nullptr, kv1_w, nullptr, nullptr, 32, 0);
    k_gemm<11,0,3, 0,0,0><<<dim3(4,64,1), 256>>>(nullptr, kv2_w, nullptr, nullptr, 32, 0);

    // v = v + depthwise_conv(v)
    k_lvadd<0><<<(8 * 4 * 256 * 64) / 256, 256>>>(lc1_w, lc1_b);
    k_lvadd<1><<<(8 * 4 * 1024 * 64) / 256, 256>>>(lc2_w, lc2_b);

    // flash attention
    k_flash<256, 0><<<dim3(64, 32), 256, fl_smem>>>();
    k_flash<1024, 1><<<dim3(64, 32), 256, fl_smem>>>();

    // out projection + bias
    k_gemm<12,0,0, 0,0,0><<<dim3(4,256,1), 256>>>(nullptr, proj_w, (float*)d_out, proj_b, 32, 0);
}